// round 9
// baseline (speedup 1.0000x reference)
#include <cuda_runtime.h>
#include <math.h>

#define TT   512
#define OUTD 500
#define NTHR 320

typedef unsigned long long ull;

// ---------------- packed f32x2 helpers (FFMA2) ----------------
__device__ __forceinline__ ull pack2(float lo, float hi) {
    ull u;
    asm("mov.b64 %0,{%1,%2};" : "=l"(u) : "f"(lo), "f"(hi));
    return u;
}
__device__ __forceinline__ ull ffma2(ull a, ull b, ull c) {
    ull d;
    asm("fma.rn.f32x2 %0,%1,%2,%3;" : "=l"(d) : "l"(a), "l"(b), "l"(c));
    return d;
}
__device__ __forceinline__ float red2(ull u) {
    float lo, hi;
    asm("mov.b64 {%0,%1},%2;" : "=f"(lo), "=f"(hi) : "l"(u));
    return lo + hi;
}

// weights packed in registers, vector in shared (LDS.64 direct into FFMA2 operand)
template <int NP>
__device__ __forceinline__ float dot_rw(const ull* __restrict__ w,
                                        const ull* __restrict__ v) {
    ull a0 = 0ull, a1 = 0ull;
#pragma unroll
    for (int p = 0; p < NP; p += 2) {
        a0 = ffma2(w[p], v[p], a0);
        if (p + 1 < NP) a1 = ffma2(w[p + 1], v[p + 1], a1);
    }
    return red2(a0) + red2(a1);
}
// both operands in shared
template <int NP>
__device__ __forceinline__ float dot_su(const ull* __restrict__ w,
                                        const ull* __restrict__ v) {
    ull a0 = 0ull, a1 = 0ull;
#pragma unroll
    for (int p = 0; p < NP; p += 2) {
        a0 = ffma2(w[p], v[p], a0);
        if (p + 1 < NP) a1 = ffma2(w[p + 1], v[p + 1], a1);
    }
    return red2(a0) + red2(a1);
}

// ---------------- fast activations (MUFU-based) ----------------
__device__ __forceinline__ float sigm(float x) {
    return __fdividef(1.0f, 1.0f + __expf(-x));
}
__device__ __forceinline__ float tanh_f(float x) {
    x = fminf(fmaxf(x, -15.0f), 15.0f);
    float e = __expf(2.0f * x);
    return __fdividef(e - 1.0f, e + 1.0f);
}
__device__ __forceinline__ float softplus_f(float x) {
    return fmaxf(x, 0.0f) + __logf(1.0f + __expf(-fabsf(x)));
}

#define BARVC() asm volatile("bar.sync %0, 160;" :: "r"(1 + vc) : "memory")
#define BARW()  asm volatile("bar.sync %0, 64;"  :: "r"(3 + vc) : "memory")

__global__ void __launch_bounds__(NTHR, 1)
arfssm_kernel(const float* __restrict__ x, const float* __restrict__ eps,
              const float* __restrict__ W_ih1, const float* __restrict__ W_hh1,
              const float* __restrict__ b_ih1, const float* __restrict__ b_hh1,
              const float* __restrict__ W_ih2, const float* __restrict__ W_hh2,
              const float* __restrict__ b_ih2, const float* __restrict__ b_hh2,
              const float* __restrict__ dzW1, const float* __restrict__ dzb1,
              const float* __restrict__ dzWloc, const float* __restrict__ dzbloc,
              const float* __restrict__ dzWsc, const float* __restrict__ dzbsc,
              const float* __restrict__ dxW1, const float* __restrict__ dxb1,
              const float* __restrict__ dxWloc, const float* __restrict__ dxbloc,
              const float* __restrict__ dxWsc, const float* __restrict__ dxbsc,
              const float* __restrict__ h1_0, const float* __restrict__ h2_0,
              float* __restrict__ out) {
    // static weights
    __shared__ __align__(16) float s_Wih2[3000];
    __shared__ __align__(16) float s_Whh1[304], s_Whh2[304];
    __shared__ __align__(16) float s_dzW1[200];
    __shared__ __align__(16) float s_dxW1[400];
    __shared__ __align__(16) float s_tail[320];   // 16 rows x 20: dzWloc96-99, dzWsc, dxWloc, dxWsc
    __shared__ float s_tailb[16];
    __shared__ float s_bih1[32], s_bih2[32], s_bhh1[32], s_bhh2[32];
    __shared__ float s_dzb1[20], s_dxb1[20];
    // dynamic, per-VC
    __shared__ __align__(16) float s_x[2][2][100];
    __shared__ __align__(16) float s_z[2][104];
    __shared__ __align__(16) float s_hdz[2][20];
    __shared__ __align__(16) float s_hdx[2][2][20];
    __shared__ float s_g1[2][32], s_g2[2][32], s_gh2[2][32];
    __shared__ float s_gh1[2][2][32];
    __shared__ float s_h2[2][2][12];

    const int tid  = threadIdx.x;
    const int vc   = tid / 160;
    const int lt   = tid - vc * 160;
    const int lane = tid & 31;
    const int b    = blockIdx.x * 2 + vc;
    const int u    = lt - 96;            // worker index (valid if lt>=96)
    const int ww   = (lt >= 128) ? 1 : 0; // worker warp within VC

    // -------- cooperative static loads --------
    for (int i = tid; i < 3000; i += NTHR) s_Wih2[i] = W_ih2[i];
    for (int i = tid; i < 300; i += NTHR) { s_Whh1[i] = W_hh1[i]; s_Whh2[i] = W_hh2[i]; }
    for (int i = tid; i < 200; i += NTHR) s_dzW1[i] = dzW1[i];
    for (int i = tid; i < 400; i += NTHR) s_dxW1[i] = dxW1[i];
    if (tid < 30) {
        s_bih1[tid] = b_ih1[tid]; s_bih2[tid] = b_ih2[tid];
        s_bhh1[tid] = b_hh1[tid]; s_bhh2[tid] = b_hh2[tid];
    }
    if (tid < 20) { s_dzb1[tid] = dzb1[tid]; s_dxb1[tid] = dxb1[tid]; }
    for (int i = tid; i < 320; i += NTHR) {
        int m = i / 20, k = i % 20, j = 96 + (m & 3);
        const float* src = (m < 4) ? dzWloc : (m < 8) ? dzWsc : (m < 12) ? dxWloc : dxWsc;
        s_tail[i] = src[j * 20 + k];
    }
    if (tid < 16) {
        int m = tid, j = 96 + (m & 3);
        const float* sb = (m < 4) ? dzbloc : (m < 8) ? dzbsc : (m < 12) ? dxbloc : dxbsc;
        s_tailb[m] = sb[j];
    }
    // s_x parities 0,1 = x(t=0), x(t=1)
    for (int i = tid; i < 400; i += NTHR) {
        int vv = i / 200, r = i % 200, par = r / 100, k = r % 100;
        s_x[vv][par][k] = x[((size_t)(blockIdx.x * 2 + vv) * TT + par) * 100 + k];
    }
    // per-VC init: h2 state, gh1(0), hdz(0)
    if (lt < 10) s_h2[vc][0][lt] = h2_0[lt];
    if (lt < 30) {
        float a = b_hh1[lt];
#pragma unroll
        for (int k = 0; k < 10; k++) a = fmaf(W_hh1[lt * 10 + k], h1_0[k], a);
        s_gh1[vc][0][lt] = a;
    } else if (lt < 50) {
        int j = lt - 30;
        float a = dzb1[j];
#pragma unroll
        for (int k = 0; k < 10; k++) a = fmaf(dzW1[j * 10 + k], h1_0[k], a);
        s_hdz[vc][j] = fmaxf(a, 0.0f);
    }

    // -------- register-resident weights --------
    ull wzl[10], wzs[10], wxl[10], wxs[10];
    float bzl = 0.f, bzs = 0.f, bxl = 0.f, bxs = 0.f, er = 0.f;
    ull wa[25];
    float h1p = 0.f, h2p[3] = {0.f, 0.f, 0.f}, er_t = 0.f;
    float4 xpre = make_float4(0.f, 0.f, 0.f, 0.f);

    if (lt < 96) {
        const float2* p;
        p = reinterpret_cast<const float2*>(dzWloc + lt * 20);
#pragma unroll
        for (int q = 0; q < 10; q++) { float2 t = p[q]; wzl[q] = pack2(t.x, t.y); }
        p = reinterpret_cast<const float2*>(dzWsc + lt * 20);
#pragma unroll
        for (int q = 0; q < 10; q++) { float2 t = p[q]; wzs[q] = pack2(t.x, t.y); }
        p = reinterpret_cast<const float2*>(dxWloc + lt * 20);
#pragma unroll
        for (int q = 0; q < 10; q++) { float2 t = p[q]; wxl[q] = pack2(t.x, t.y); }
        p = reinterpret_cast<const float2*>(dxWsc + lt * 20);
#pragma unroll
        for (int q = 0; q < 10; q++) { float2 t = p[q]; wxs[q] = pack2(t.x, t.y); }
        bzl = dzbloc[lt]; bzs = dzbsc[lt]; bxl = dxbloc[lt]; bxs = dxbsc[lt];
        er = eps[((size_t)b * TT) * 100 + lt];
    } else {
        if (u < 60) {                      // gi1 split-2 weights
            int j = u >> 1, h = u & 1;
            const float2* p = reinterpret_cast<const float2*>(W_ih1 + j * 100 + h * 50);
#pragma unroll
            for (int q = 0; q < 25; q++) { float2 t = p[q]; wa[q] = pack2(t.x, t.y); }
        } else {                           // z-tail / GRU2-combine threads
            int i = u - 60;
            er_t = eps[((size_t)b * TT) * 100 + 96 + i];
            int q = 0;
            for (int j = i; j < 10; j += 4) h2p[q++] = h2_0[j];
        }
        if (lane < 10) h1p = h1_0[lane];
    }
    __syncthreads();

    for (int t = 0; t < TT; t++) {
        const int cur = t & 1, nxt = cur ^ 1;

        // ================= S1 =================
        if (lt < 96) {
            // z-head
            const ull* hz = reinterpret_cast<const ull*>(&s_hdz[vc][0]);
            float zl = dot_rw<10>(wzl, hz) + bzl;
            float zs = softplus_f(dot_rw<10>(wzs, hz) + bzs);
            float zt = fmaf(zs, er, zl);
            s_z[vc][lt] = zt;
            float* o = out + ((size_t)b * TT + t) * OUTD;
            o[200 + lt] = zl; o[300 + lt] = zs; o[400 + lt] = zt;
            if (t + 1 < TT) er = eps[((size_t)b * TT + t + 1) * 100 + lt];
            if (lt < 30) {                 // gh2 row lt
                float a = s_bhh2[lt];
#pragma unroll
                for (int k = 0; k < 10; k++) a = fmaf(s_Whh2[lt * 10 + k], s_h2[vc][cur][k], a);
                s_gh2[vc][lt] = a;
            }
        } else {
            if (u < 25 && t + 2 < TT)      // x(t+2) prefetch
                xpre = *reinterpret_cast<const float4*>(
                    x + ((size_t)b * TT + t + 2) * 100 + u * 4);
            if (u < 60) {                  // gi2 split-2 from shared
                int j = u >> 1, h = u & 1;
                const ull* w = reinterpret_cast<const ull*>(s_Wih2 + j * 100 + h * 50);
                const ull* v = reinterpret_cast<const ull*>(&s_x[vc][cur][0] + h * 50);
                float val = dot_su<25>(w, v);
                unsigned mask = (u < 32) ? 0xFFFFFFFFu : 0x0FFFFFFFu;
                val += __shfl_xor_sync(mask, val, 1);
                if (h == 0) s_g2[vc][j] = val + s_bih2[j];
            } else {                       // z-tail j = 96+i (u=60..63)
                int i = u - 60;
                const ull* hz = reinterpret_cast<const ull*>(&s_hdz[vc][0]);
                float zl = dot_su<10>(reinterpret_cast<const ull*>(&s_tail[i * 20]), hz) + s_tailb[i];
                float zs = softplus_f(
                    dot_su<10>(reinterpret_cast<const ull*>(&s_tail[(4 + i) * 20]), hz) + s_tailb[4 + i]);
                float zt = fmaf(zs, er_t, zl);
                s_z[vc][96 + i] = zt;
                float* o = out + ((size_t)b * TT + t) * OUTD;
                o[296 + i] = zl; o[396 + i] = zs; o[496 + i] = zt;
                if (t + 1 < TT) er_t = eps[((size_t)b * TT + t + 1) * 100 + 96 + i];
            }
        }
        BARVC();

        // ================= S2 =================
        if (lt < 96) {
            if (t > 0) {                   // x-head for t-1 (parity nxt)
                const ull* hv = reinterpret_cast<const ull*>(&s_hdx[vc][nxt][0]);
                float xl = dot_rw<10>(wxl, hv) + bxl;
                float xs = softplus_f(dot_rw<10>(wxs, hv) + bxs);
                float* o = out + ((size_t)b * TT + (t - 1)) * OUTD;
                o[lt] = xl; o[100 + lt] = xs;
            }
        } else {
            // ---- pre-bar64 ----
            if (u < 60) {                  // gi1 split-2 (register weights)
                int j = u >> 1, h = u & 1;
                const ull* v = reinterpret_cast<const ull*>(&s_z[vc][0] + h * 50);
                float val = dot_rw<25>(wa, v);
                unsigned mask = (u < 32) ? 0xFFFFFFFFu : 0x0FFFFFFFu;
                val += __shfl_xor_sync(mask, val, 1);
                if (h == 0) s_g1[vc][j] = val + s_bih1[j];
            } else {                       // GRU2 combine (u=60..63, rows i,i+4,i+8)
                int i = u - 60, q = 0;
                for (int j = i; j < 10; j += 4, q++) {
                    float r  = sigm(s_g2[vc][j] + s_gh2[vc][j]);
                    float uu = sigm(s_g2[vc][10 + j] + s_gh2[vc][10 + j]);
                    float n  = tanh_f(fmaf(r, s_gh2[vc][20 + j], s_g2[vc][20 + j]));
                    float hn = fmaf(uu, h2p[q] - n, n);
                    h2p[q] = hn;
                    s_h2[vc][nxt][j] = hn;
                }
            }
            BARW();
            // ---- post-bar64: GRU1 combine + fanout from registers ----
            float h1n = 0.0f;
            if (lane < 10) {
                int j = lane;
                float r  = sigm(s_g1[vc][j] + s_gh1[vc][cur][j]);
                float uu = sigm(s_g1[vc][10 + j] + s_gh1[vc][cur][10 + j]);
                float n  = tanh_f(fmaf(r, s_gh1[vc][cur][20 + j], s_g1[vc][20 + j]));
                h1n = fmaf(uu, h1p - n, n);
                h1p = h1n;
            }
            float hk[10];
#pragma unroll
            for (int k = 0; k < 10; k++) hk[k] = __shfl_sync(0xFFFFFFFFu, h1n, k);
            if (lane < 10) {
                int j = ww * 10 + lane;    // hdx + hdz rows
                float a = s_dxb1[j];
#pragma unroll
                for (int k = 0; k < 10; k++) a = fmaf(s_dxW1[j * 20 + k], hk[k], a);
#pragma unroll
                for (int k = 0; k < 10; k++) a = fmaf(s_dxW1[j * 20 + 10 + k], s_h2[vc][cur][k], a);
                s_hdx[vc][cur][j] = fmaxf(a, 0.0f);
                float d = s_dzb1[j];
#pragma unroll
                for (int k = 0; k < 10; k++) d = fmaf(s_dzW1[j * 10 + k], hk[k], d);
                s_hdz[vc][j] = fmaxf(d, 0.0f);
            } else if (lane < 14) {        // x-tail j = 96..99 for t-1
                if (t > 0) {
                    int i = lane - 10;
                    const ull* hv = reinterpret_cast<const ull*>(&s_hdx[vc][nxt][0]);
                    float* o = out + ((size_t)b * TT + (t - 1)) * OUTD;
                    if (ww == 0) {
                        float xl = dot_su<10>(reinterpret_cast<const ull*>(&s_tail[(8 + i) * 20]), hv)
                                   + s_tailb[8 + i];
                        o[96 + i] = xl;
                    } else {
                        float xs = softplus_f(
                            dot_su<10>(reinterpret_cast<const ull*>(&s_tail[(12 + i) * 20]), hv)
                            + s_tailb[12 + i]);
                        o[196 + i] = xs;
                    }
                }
            } else {                       // gh1 rows for t+1
                int j = ww ? (lane - 14 + 18) : (lane - 14);
                if (j < 30) {
                    float a = s_bhh1[j];
#pragma unroll
                    for (int k = 0; k < 10; k++) a = fmaf(s_Whh1[j * 10 + k], hk[k], a);
                    s_gh1[vc][nxt][j] = a;
                }
            }
            if (u < 25 && t + 2 < TT)      // stash prefetched x(t+2)
                reinterpret_cast<float4*>(&s_x[vc][cur][0])[u] = xpre;
        }
        BARVC();
    }

    // ---- epilogue: x outputs for t = TT-1 ----
    {
        const int prev = (TT - 1) & 1;
        float* o = out + ((size_t)b * TT + (TT - 1)) * OUTD;
        if (lt < 96) {
            const ull* hv = reinterpret_cast<const ull*>(&s_hdx[vc][prev][0]);
            float xl = dot_rw<10>(wxl, hv) + bxl;
            float xs = softplus_f(dot_rw<10>(wxs, hv) + bxs);
            o[lt] = xl; o[100 + lt] = xs;
        } else if (lane >= 10 && lane < 14) {
            int i = lane - 10;
            const ull* hv = reinterpret_cast<const ull*>(&s_hdx[vc][prev][0]);
            if (ww == 0) {
                o[96 + i] = dot_su<10>(reinterpret_cast<const ull*>(&s_tail[(8 + i) * 20]), hv)
                            + s_tailb[8 + i];
            } else {
                o[196 + i] = softplus_f(
                    dot_su<10>(reinterpret_cast<const ull*>(&s_tail[(12 + i) * 20]), hv)
                    + s_tailb[12 + i]);
            }
        }
    }
}

extern "C" void kernel_launch(void* const* d_in, const int* in_sizes, int n_in,
                              void* d_out, int out_size) {
    const float* x      = (const float*)d_in[0];
    const float* eps    = (const float*)d_in[1];
    const float* W_ih1  = (const float*)d_in[2];
    const float* W_hh1  = (const float*)d_in[3];
    const float* b_ih1  = (const float*)d_in[4];
    const float* b_hh1  = (const float*)d_in[5];
    const float* W_ih2  = (const float*)d_in[6];
    const float* W_hh2  = (const float*)d_in[7];
    const float* b_ih2  = (const float*)d_in[8];
    const float* b_hh2  = (const float*)d_in[9];
    const float* dzW1   = (const float*)d_in[10];
    const float* dzb1   = (const float*)d_in[11];
    const float* dzWloc = (const float*)d_in[12];
    const float* dzbloc = (const float*)d_in[13];
    const float* dzWsc  = (const float*)d_in[14];
    const float* dzbsc  = (const float*)d_in[15];
    const float* dxW1   = (const float*)d_in[16];
    const float* dxb1   = (const float*)d_in[17];
    const float* dxWloc = (const float*)d_in[18];
    const float* dxbloc = (const float*)d_in[19];
    const float* dxWsc  = (const float*)d_in[20];
    const float* dxbsc  = (const float*)d_in[21];
    const float* h1_0   = (const float*)d_in[22];
    const float* h2_0   = (const float*)d_in[23];

    int Btot = in_sizes[0] / (TT * 100);   // 256
    int grid = Btot / 2;                   // 128 blocks, 2 VCs each

    arfssm_kernel<<<grid, NTHR>>>(x, eps, W_ih1, W_hh1, b_ih1, b_hh1,
                                  W_ih2, W_hh2, b_ih2, b_hh2,
                                  dzW1, dzb1, dzWloc, dzbloc, dzWsc, dzbsc,
                                  dxW1, dxb1, dxWloc, dxbloc, dxWsc, dxbsc,
                                  h1_0, h2_0, (float*)d_out);
}

// round 11
// speedup vs baseline: 1.0455x; 1.0455x over previous
#include <cuda_runtime.h>
#include <math.h>

#define TT   512
#define OUTD 500
#define NTHR 352

typedef unsigned long long ull;

// ---------------- packed f32x2 helpers (FFMA2) ----------------
__device__ __forceinline__ ull pack2(float lo, float hi) {
    ull u;
    asm("mov.b64 %0,{%1,%2};" : "=l"(u) : "f"(lo), "f"(hi));
    return u;
}
__device__ __forceinline__ ull ffma2(ull a, ull b, ull c) {
    ull d;
    asm("fma.rn.f32x2 %0,%1,%2,%3;" : "=l"(d) : "l"(a), "l"(b), "l"(c));
    return d;
}
__device__ __forceinline__ float red2(ull u) {
    float lo, hi;
    asm("mov.b64 {%0,%1},%2;" : "=f"(lo), "=f"(hi) : "l"(u));
    return lo + hi;
}

// 2-accumulator dot: weights in registers, vector in shared (LDS.64)
template <int NP>
__device__ __forceinline__ float dot_rw(const ull* __restrict__ w,
                                        const ull* __restrict__ v) {
    ull a0 = 0ull, a1 = 0ull;
#pragma unroll
    for (int p = 0; p < NP; p += 2) {
        a0 = ffma2(w[p], v[p], a0);
        if (p + 1 < NP) a1 = ffma2(w[p + 1], v[p + 1], a1);
    }
    return red2(a0) + red2(a1);
}
// 4-accumulator dot for the long K=100 reductions
template <int NP>
__device__ __forceinline__ float dot_rw4(const ull* __restrict__ w,
                                         const ull* __restrict__ v) {
    ull a0 = 0ull, a1 = 0ull, a2 = 0ull, a3 = 0ull;
#pragma unroll
    for (int p = 0; p < NP; p += 4) {
        a0 = ffma2(w[p], v[p], a0);
        if (p + 1 < NP) a1 = ffma2(w[p + 1], v[p + 1], a1);
        if (p + 2 < NP) a2 = ffma2(w[p + 2], v[p + 2], a2);
        if (p + 3 < NP) a3 = ffma2(w[p + 3], v[p + 3], a3);
    }
    return (red2(a0) + red2(a1)) + (red2(a2) + red2(a3));
}

// ---------------- fast activations (MUFU-based) ----------------
__device__ __forceinline__ float sigm(float x) {
    return __fdividef(1.0f, 1.0f + __expf(-x));
}
__device__ __forceinline__ float tanh_f(float x) {
    x = fminf(fmaxf(x, -15.0f), 15.0f);
    float e = __expf(2.0f * x);
    return __fdividef(e - 1.0f, e + 1.0f);
}
__device__ __forceinline__ float softplus_f(float x) {
    return fmaxf(x, 0.0f) + __logf(1.0f + __expf(-fabsf(x)));
}

__global__ void __launch_bounds__(NTHR, 1)
arfssm_kernel(const float* __restrict__ x, const float* __restrict__ eps,
              const float* __restrict__ W_ih1, const float* __restrict__ W_hh1,
              const float* __restrict__ b_ih1, const float* __restrict__ b_hh1,
              const float* __restrict__ W_ih2, const float* __restrict__ W_hh2,
              const float* __restrict__ b_ih2, const float* __restrict__ b_hh2,
              const float* __restrict__ dzW1, const float* __restrict__ dzb1,
              const float* __restrict__ dzWloc, const float* __restrict__ dzbloc,
              const float* __restrict__ dzWsc, const float* __restrict__ dzbsc,
              const float* __restrict__ dxW1, const float* __restrict__ dxb1,
              const float* __restrict__ dxWloc, const float* __restrict__ dxbloc,
              const float* __restrict__ dxWsc, const float* __restrict__ dxbsc,
              const float* __restrict__ h1_0, const float* __restrict__ h2_0,
              float* __restrict__ out) {
    __shared__ __align__(16) float s_z[2][104];        // [b][100] (pad 104)
    __shared__ __align__(16) float s_hdz[2][20];       // [b]
    __shared__ __align__(16) float s_hdx[2][2][20];    // [parity][b]
    __shared__ __align__(16) float s_h2[2][2][12];     // [parity][b]  (h2 with 1-step delay)
    __shared__ __align__(16) float s_x[3][2][104];     // triple buffer [t%3][b][100]

    const int tid  = threadIdx.x;
    const int lane = tid & 31;
    const int wid  = tid >> 5;
    const int b0   = blockIdx.x * 2;

    // ---- cooperative preload of x slots 0,1 ----
    for (int i = tid; i < 100; i += NTHR) {
        int s = i / 50, r = i % 50, bb = r / 25, f = r % 25;
        ((float4*)&s_x[s][bb][0])[f] =
            ((const float4*)(x + ((size_t)(b0 + bb) * TT + s) * 100))[f];
    }

    // ---------------- per-role register state ----------------
    // heads (tid 0..199)
    ull wzl[10], wzs[10], wxl[10], wxs[10];
    float bzl = 0.f, bzs = 0.f, bxl = 0.f, bxs = 0.f, er = 0.f;
    int hb = 0, hj = 0;
    // recurrence warps (wid 7,8)
    ull wa[50];                                // FULL K=100 row (50 f32x2 pairs)
    float whh1r[10], dzr[10], dxr1[10], dxr2[10];
    float bih1r = 0.f, bhh1r = 0.f, dzb1r = 0.f, dxb1r = 0.f;
    float h1p = 0.f, gh1own = 0.f;
    // RNN2 warps (wid 9,10)
    ull wih2r[50];                             // FULL K=100 row
    float whh2r[10], h2all[10];
    float bih2r = 0.f, bhh2r = 0.f, h2own = 0.f;
    int rb = 0;
#pragma unroll
    for (int q = 0; q < 50; q++) { wa[q] = 0ull; wih2r[q] = 0ull; }
#pragma unroll
    for (int k = 0; k < 10; k++) {
        whh1r[k] = dzr[k] = dxr1[k] = dxr2[k] = whh2r[k] = h2all[k] = 0.f;
    }

    if (tid < 200) {
        hb = tid / 100; hj = tid % 100;
        const float2* p;
        p = (const float2*)(dzWloc + hj * 20);
#pragma unroll
        for (int q = 0; q < 10; q++) { float2 v = p[q]; wzl[q] = pack2(v.x, v.y); }
        p = (const float2*)(dzWsc + hj * 20);
#pragma unroll
        for (int q = 0; q < 10; q++) { float2 v = p[q]; wzs[q] = pack2(v.x, v.y); }
        p = (const float2*)(dxWloc + hj * 20);
#pragma unroll
        for (int q = 0; q < 10; q++) { float2 v = p[q]; wxl[q] = pack2(v.x, v.y); }
        p = (const float2*)(dxWsc + hj * 20);
#pragma unroll
        for (int q = 0; q < 10; q++) { float2 v = p[q]; wxs[q] = pack2(v.x, v.y); }
        bzl = dzbloc[hj]; bzs = dzbsc[hj]; bxl = dxbloc[hj]; bxs = dxbsc[hj];
        er = eps[((size_t)(b0 + hb) * TT) * 100 + hj];
    } else if (wid == 7 || wid == 8) {
        rb = wid - 7;
        if (lane < 30) {
            const float2* p = (const float2*)(W_ih1 + lane * 100);
#pragma unroll
            for (int q = 0; q < 50; q++) { float2 v = p[q]; wa[q] = pack2(v.x, v.y); }
#pragma unroll
            for (int k = 0; k < 10; k++) whh1r[k] = W_hh1[lane * 10 + k];
            bih1r = b_ih1[lane]; bhh1r = b_hh1[lane];
            float a = bhh1r;
#pragma unroll
            for (int k = 0; k < 10; k++) a = fmaf(whh1r[k], h1_0[k], a);
            gh1own = a;                      // gh1 for t=0
        }
        if (lane < 20) {
#pragma unroll
            for (int k = 0; k < 10; k++) {
                dzr[k]  = dzW1[lane * 10 + k];
                dxr1[k] = dxW1[lane * 20 + k];
                dxr2[k] = dxW1[lane * 20 + 10 + k];
            }
            dzb1r = dzb1[lane]; dxb1r = dxb1[lane];
            float a = dzb1r;
#pragma unroll
            for (int k = 0; k < 10; k++) a = fmaf(dzr[k], h1_0[k], a);
            s_hdz[rb][lane] = fmaxf(a, 0.0f);    // hdz for t=0
        }
        if (lane < 10) h1p = h1_0[lane];
    } else if (wid >= 9) {
        rb = wid - 9;
        if (lane < 30) {
            const float2* p = (const float2*)(W_ih2 + lane * 100);
#pragma unroll
            for (int q = 0; q < 50; q++) { float2 v = p[q]; wih2r[q] = pack2(v.x, v.y); }
#pragma unroll
            for (int k = 0; k < 10; k++) whh2r[k] = W_hh2[lane * 10 + k];
            bih2r = b_ih2[lane]; bhh2r = b_hh2[lane];
        }
#pragma unroll
        for (int k = 0; k < 10; k++) h2all[k] = h2_0[k];
        if (lane < 10) {
            h2own = h2_0[lane];
            s_h2[0][rb][lane] = h2own;           // h2_shift for t=0
        }
    }
    __syncthreads();

    float4 pre = make_float4(0.f, 0.f, 0.f, 0.f);
    float ghA = 0.f, ghB = 0.f, hdx2 = 0.f;

    for (int t = 0; t < TT; t++) {
        const int cur = t & 1, nxt = cur ^ 1;

        // ================= S1 =================
        if (tid < 200) {                        // z-head
            const ull* hz = (const ull*)&s_hdz[hb][0];
            float zl = dot_rw<10>(wzl, hz) + bzl;
            float zs = softplus_f(dot_rw<10>(wzs, hz) + bzs);
            float zt = fmaf(zs, er, zl);
            s_z[hb][hj] = zt;
            float* o = out + ((size_t)(b0 + hb) * TT + t) * OUTD;
            o[200 + hj] = zl; o[300 + hj] = zs; o[400 + hj] = zt;
            if (t + 1 < TT)
                er = eps[((size_t)(b0 + hb) * TT + t + 1) * 100 + hj];
        } else if (wid == 7 || wid == 8) {      // REC: pre-gather for S2
            ghA = __shfl_sync(0xFFFFFFFFu, gh1own, lane + 10);
            ghB = __shfl_sync(0xFFFFFFFFu, gh1own, lane + 20);
            float c = dxb1r;
            if (lane < 20) {
#pragma unroll
                for (int k = 0; k < 10; k++) c = fmaf(dxr2[k], s_h2[cur][rb][k], c);
            }
            hdx2 = c;
        } else if (wid >= 9) {                  // x(t+2) prefetch issue
            if (lane < 25 && t + 2 < TT)
                pre = ((const float4*)(x + ((size_t)(b0 + rb) * TT + t + 2) * 100))[lane];
        }
        __syncthreads();

        // ================= S2 =================
        if (tid < 200) {                        // x-head for t-1 (pipelined)
            if (t > 0) {
                const ull* hv = (const ull*)&s_hdx[nxt][hb][0];
                float xl = dot_rw<10>(wxl, hv) + bxl;
                float xs = softplus_f(dot_rw<10>(wxs, hv) + bxs);
                float* o = out + ((size_t)(b0 + hb) * TT + (t - 1)) * OUTD;
                o[hj] = xl; o[100 + hj] = xs;
            }
        } else if (wid == 7 || wid == 8) {      // REC: gi1 -> GRU1 -> fanout
            const ull* zr = (const ull*)&s_z[rb][0];
            float g = dot_rw4<50>(wa, zr) + bih1r;
            float gA = __shfl_sync(0xFFFFFFFFu, g, lane + 10);
            float gB = __shfl_sync(0xFFFFFFFFu, g, lane + 20);
            float r  = sigm(g + gh1own);
            float uu = sigm(gA + ghA);
            float n  = tanh_f(fmaf(r, ghB, gB));
            float h1n = fmaf(uu, h1p - n, n);
            h1p = h1n;
            float hk[10];
#pragma unroll
            for (int k = 0; k < 10; k++) hk[k] = __shfl_sync(0xFFFFFFFFu, h1n, k);
            if (lane < 20) {
                float a = dzb1r;
#pragma unroll
                for (int k = 0; k < 10; k++) a = fmaf(dzr[k], hk[k], a);
                s_hdz[rb][lane] = fmaxf(a, 0.0f);
                float c = hdx2;
#pragma unroll
                for (int k = 0; k < 10; k++) c = fmaf(dxr1[k], hk[k], c);
                s_hdx[cur][rb][lane] = fmaxf(c, 0.0f);
            }
            float a2 = bhh1r;                   // gh1 for t+1
#pragma unroll
            for (int k = 0; k < 10; k++) a2 = fmaf(whh1r[k], hk[k], a2);
            gh1own = a2;
        } else if (wid >= 9) {                  // RNN2 (fully async) + prefetch stash
            const ull* xr = (const ull*)&s_x[t % 3][rb][0];
            float g = dot_rw4<50>(wih2r, xr) + bih2r;
            float gA = __shfl_sync(0xFFFFFFFFu, g, lane + 10);
            float gB = __shfl_sync(0xFFFFFFFFu, g, lane + 20);
            float gh = bhh2r;
#pragma unroll
            for (int k = 0; k < 10; k++) gh = fmaf(whh2r[k], h2all[k], gh);
            float ghA2 = __shfl_sync(0xFFFFFFFFu, gh, lane + 10);
            float ghB2 = __shfl_sync(0xFFFFFFFFu, gh, lane + 20);
            float r  = sigm(g + gh);
            float uu = sigm(gA + ghA2);
            float n  = tanh_f(fmaf(r, ghB2, gB));
            float h2n = fmaf(uu, h2own - n, n);
            if (lane < 10) h2own = h2n;
#pragma unroll
            for (int k = 0; k < 10; k++) h2all[k] = __shfl_sync(0xFFFFFFFFu, h2n, k);
            if (lane < 10) s_h2[nxt][rb][lane] = h2n;   // published for step t+1
            if (lane < 25 && t + 2 < TT)
                ((float4*)&s_x[(t + 2) % 3][rb][0])[lane] = pre;
        }
        __syncthreads();
    }

    // ---- epilogue: x outputs for t = TT-1 ----
    if (tid < 200) {
        const int p = (TT - 1) & 1;
        const ull* hv = (const ull*)&s_hdx[p][hb][0];
        float xl = dot_rw<10>(wxl, hv) + bxl;
        float xs = softplus_f(dot_rw<10>(wxs, hv) + bxs);
        float* o = out + ((size_t)(b0 + hb) * TT + (TT - 1)) * OUTD;
        o[hj] = xl; o[100 + hj] = xs;
    }
}

extern "C" void kernel_launch(void* const* d_in, const int* in_sizes, int n_in,
                              void* d_out, int out_size) {
    const float* x      = (const float*)d_in[0];
    const float* eps    = (const float*)d_in[1];
    const float* W_ih1  = (const float*)d_in[2];
    const float* W_hh1  = (const float*)d_in[3];
    const float* b_ih1  = (const float*)d_in[4];
    const float* b_hh1  = (const float*)d_in[5];
    const float* W_ih2  = (const float*)d_in[6];
    const float* W_hh2  = (const float*)d_in[7];
    const float* b_ih2  = (const float*)d_in[8];
    const float* b_hh2  = (const float*)d_in[9];
    const float* dzW1   = (const float*)d_in[10];
    const float* dzb1   = (const float*)d_in[11];
    const float* dzWloc = (const float*)d_in[12];
    const float* dzbloc = (const float*)d_in[13];
    const float* dzWsc  = (const float*)d_in[14];
    const float* dzbsc  = (const float*)d_in[15];
    const float* dxW1   = (const float*)d_in[16];
    const float* dxb1   = (const float*)d_in[17];
    const float* dxWloc = (const float*)d_in[18];
    const float* dxbloc = (const float*)d_in[19];
    const float* dxWsc  = (const float*)d_in[20];
    const float* dxbsc  = (const float*)d_in[21];
    const float* h1_0   = (const float*)d_in[22];
    const float* h2_0   = (const float*)d_in[23];

    int Btot = in_sizes[0] / (TT * 100);   // 256
    int grid = Btot / 2;                   // 128 blocks, 2 batches each

    arfssm_kernel<<<grid, NTHR>>>(x, eps, W_ih1, W_hh1, b_ih1, b_hh1,
                                  W_ih2, W_hh2, b_ih2, b_hh2,
                                  dzW1, dzb1, dzWloc, dzbloc, dzWsc, dzbsc,
                                  dxW1, dxb1, dxWloc, dxbloc, dxWsc, dxbsc,
                                  h1_0, h2_0, (float*)d_out);
}